// round 15
// baseline (speedup 1.0000x reference)
#include <cuda_runtime.h>
#include <cuda_fp16.h>
#include <stdint.h>

// R15: fat warps (4 warps x 32 rows) -> 0.31 x4-LDSM per MMA (was 1.0);
// single-buffered K/V (95.7KB smem) so 2 CTAs/SM co-reside: cross-CTA
// overlap of MMA vs LDSM/staging, and all 256 CTAs fit in one wave.

static constexpr int BATCH = 16;
static constexpr int LSEQ  = 2048;
static constexpr int DHEAD = 128;
static constexpr int TQ    = 128;   // 4 warps x 32 rows
static constexpr int TKN   = 32;
static constexpr int NKT   = LSEQ / TKN;   // 64
static constexpr int THREADS = 128;

static constexpr int PAD   = 136;
static constexpr int QT_BYTES = TQ  * PAD * 2;   // 34816
static constexpr int KT_BYTES = TKN * PAD * 2;   // 8704
static constexpr int SQH = 0;
static constexpr int SQL = QT_BYTES;
static constexpr int SKV = 2 * QT_BYTES;                 // 69632
static constexpr int OKH = 0, OKL = KT_BYTES, OV = 2 * KT_BYTES;
static constexpr int SMEM_BYTES = SKV + 3 * KT_BYTES;    // 95744 -> 2 CTAs/SM

__device__ __align__(16) __half g_qh[(size_t)BATCH * LSEQ * DHEAD];
__device__ __align__(16) __half g_ql[(size_t)BATCH * LSEQ * DHEAD];
__device__ __align__(16) __half g_kh[(size_t)BATCH * LSEQ * DHEAD];
__device__ __align__(16) __half g_kl[(size_t)BATCH * LSEQ * DHEAD];
__device__ __align__(16) __half g_v [(size_t)BATCH * LSEQ * DHEAD];

// ---------------- helpers ----------------
__device__ __forceinline__ uint32_t smem_u32(const void* p) {
    uint32_t a;
    asm("{ .reg .u64 t; cvta.to.shared.u64 t, %1; cvt.u32.u64 %0, t; }" : "=r"(a) : "l"(p));
    return a;
}
__device__ __forceinline__ uint32_t pack2h(__half a, __half b) {
    return (uint32_t)__half_as_ushort(a) | ((uint32_t)__half_as_ushort(b) << 16);
}
__device__ __forceinline__ void ldsm_x4(uint32_t* r, uint32_t addr) {
    asm volatile("ldmatrix.sync.aligned.m8n8.x4.shared.b16 {%0,%1,%2,%3}, [%4];"
                 : "=r"(r[0]), "=r"(r[1]), "=r"(r[2]), "=r"(r[3]) : "r"(addr));
}
__device__ __forceinline__ void ldsm_x4_t(uint32_t* r, uint32_t addr) {
    asm volatile("ldmatrix.sync.aligned.m8n8.x4.trans.shared.b16 {%0,%1,%2,%3}, [%4];"
                 : "=r"(r[0]), "=r"(r[1]), "=r"(r[2]), "=r"(r[3]) : "r"(addr));
}
__device__ __forceinline__ void mma16816(float* d, const uint32_t* a, const uint32_t* b) {
    asm volatile("mma.sync.aligned.m16n8k16.row.col.f32.f16.f16.f32 "
                 "{%0,%1,%2,%3}, {%4,%5,%6,%7}, {%8,%9}, {%0,%1,%2,%3};"
                 : "+f"(d[0]), "+f"(d[1]), "+f"(d[2]), "+f"(d[3])
                 : "r"(a[0]), "r"(a[1]), "r"(a[2]), "r"(a[3]), "r"(b[0]), "r"(b[1]));
}
__device__ __forceinline__ void cp16(uint32_t dst, const void* src) {
    asm volatile("cp.async.cg.shared.global [%0], [%1], 16;" :: "r"(dst), "l"(src));
}
#define CP_COMMIT() asm volatile("cp.async.commit_group;" ::: "memory")

// 32-row tile, 128 threads: 512 chunks -> 4 each
__device__ __forceinline__ void stage32(uint32_t dstb, const __half* __restrict__ g, int tid) {
    #pragma unroll
    for (int i = 0; i < 4; ++i) {
        int idx = tid + i * THREADS;
        int row = idx >> 4, c = idx & 15;
        cp16(dstb + row * (PAD * 2) + c * 16, g + row * DHEAD + c * 8);
    }
}
// 128-row tile: 2048 chunks -> 16 each
__device__ __forceinline__ void stage128q(uint32_t dstb, const __half* __restrict__ g, int tid) {
    #pragma unroll
    for (int i = 0; i < 16; ++i) {
        int idx = tid + i * THREADS;
        int row = idx >> 4, c = idx & 15;
        cp16(dstb + row * (PAD * 2) + c * 16, g + row * DHEAD + c * 8);
    }
}

// -------- prep: fp32 -> fp16 hi/lo (Q,K) and fp16 (V) --------
__device__ __forceinline__ void split4h(float4 f, __half* hi, __half* lo, size_t i4) {
    __half h0 = __float2half_rn(f.x), h1 = __float2half_rn(f.y);
    __half h2 = __float2half_rn(f.z), h3 = __float2half_rn(f.w);
    *reinterpret_cast<uint2*>(hi + 4 * i4) = make_uint2(pack2h(h0, h1), pack2h(h2, h3));
    *reinterpret_cast<uint2*>(lo + 4 * i4) = make_uint2(
        pack2h(__float2half_rn(f.x - __half2float(h0)), __float2half_rn(f.y - __half2float(h1))),
        pack2h(__float2half_rn(f.z - __half2float(h2)), __float2half_rn(f.w - __half2float(h3))));
}
__global__ void prep_split(const float* __restrict__ q, const float* __restrict__ k,
                           const float* __restrict__ v) {
    size_t i = (size_t)blockIdx.x * blockDim.x + threadIdx.x;
    split4h(reinterpret_cast<const float4*>(q)[i], g_qh, g_ql, i);
    split4h(reinterpret_cast<const float4*>(k)[i], g_kh, g_kl, i);
    float4 fv = reinterpret_cast<const float4*>(v)[i];
    *reinterpret_cast<uint2*>(g_v + 4 * i) = make_uint2(
        pack2h(__float2half_rn(fv.x), __float2half_rn(fv.y)),
        pack2h(__float2half_rn(fv.z), __float2half_rn(fv.w)));
}

// -------- fused attention + layernorm --------
__global__ void __launch_bounds__(THREADS, 2)
fmha_ln_hmma(const float* __restrict__ MASK, const float* __restrict__ GAMMA,
             const float* __restrict__ BETA, float* __restrict__ OUT) {
    extern __shared__ char sm[];
    const int tid = threadIdx.x;
    const int w   = tid >> 5;          // 0..3, owns rows 32w..32w+31
    const int l   = tid & 31;
    const int b   = blockIdx.y;
    const int q0  = blockIdx.x * TQ;

    const int qr  = l >> 2;
    const int qc2 = (l & 3) * 2;

    const uint32_t smb = smem_u32(sm);
    const int lr = l & 7, g = l >> 3;

    uint32_t a_off[2];
    #pragma unroll
    for (int mt = 0; mt < 2; ++mt)
        a_off[mt] = (uint32_t)((32 * w + 16 * mt + lr + ((g & 1) << 3)) * PAD + ((g >> 1) << 3)) * 2;
    const uint32_t kb4_off = (uint32_t)((lr + ((g >> 1) << 3)) * PAD + ((g & 1) << 3)) * 2;
    const uint32_t vb4_off = (uint32_t)((lr + ((g & 1) << 3)) * PAD + ((g >> 1) << 3)) * 2;

    const size_t qgbase = ((size_t)(b * LSEQ + q0)) * DHEAD;
    const size_t kvbase = ((size_t)b * LSEQ) * DHEAD;

    stage128q(smb + SQH, g_qh + qgbase, tid);
    stage128q(smb + SQL, g_ql + qgbase, tid);

    float o[2][16][4];
    #pragma unroll
    for (int mt = 0; mt < 2; ++mt)
        #pragma unroll
        for (int n = 0; n < 16; ++n) { o[mt][n][0] = o[mt][n][1] = o[mt][n][2] = o[mt][n][3] = 0.f; }
    float Z[4] = {0.f, 0.f, 0.f, 0.f};
    float M[4] = {-1e30f, -1e30f, -1e30f, -1e30f};   // rg = 2*mt + hiRow

    // mask row pointers: row = q0 + 32w + 16mt + 8*(rg&1) + qr
    const float* mrL[2];
    #pragma unroll
    for (int mt = 0; mt < 2; ++mt)
        mrL[mt] = MASK + (size_t)(q0 + 32 * w + 16 * mt + qr) * LSEQ;

    #pragma unroll 1
    for (int kt = 0; kt < NKT; ++kt) {
        __syncthreads();   // previous tile's readers done (no-op cost at kt=0)
        {
            const uint32_t d0 = smb + SKV;
            const size_t tn = kvbase + (size_t)kt * TKN * DHEAD;
            stage32(d0 + OKH, g_kh + tn, tid);
            stage32(d0 + OKL, g_kl + tn, tid);
            stage32(d0 + OV,  g_v  + tn, tid);
        }
        CP_COMMIT();
        asm volatile("cp.async.wait_group 0;" ::: "memory");
        __syncthreads();

        const uint32_t kh = smb + SKV + OKH, kl = smb + SKV + OKL;
        const uint32_t vv = smb + SKV + OV;

        // ---- mask prefetch: [mt][n] for rowL/rowH ----
        float2 mA[2][4], mB[2][4];
        #pragma unroll
        for (int mt = 0; mt < 2; ++mt)
            #pragma unroll
            for (int n = 0; n < 4; ++n) {
                const int cb = kt * TKN + 8 * n + qc2;
                mA[mt][n] = *reinterpret_cast<const float2*>(mrL[mt] + cb);
                mB[mt][n] = *reinterpret_cast<const float2*>(mrL[mt] + 8 * LSEQ + cb);
            }

        // ---- S = Qhi*Khi + Qhi*Klo + Qlo*Khi ----
        float c[2][4][4];
        #pragma unroll
        for (int mt = 0; mt < 2; ++mt)
            #pragma unroll
            for (int n = 0; n < 4; ++n) { c[mt][n][0] = c[mt][n][1] = c[mt][n][2] = c[mt][n][3] = 0.f; }

        #pragma unroll
        for (int kk = 0; kk < 8; ++kk) {
            uint32_t aH[2][4], aL[2][4];
            ldsm_x4(aH[0], smb + SQH + a_off[0] + kk * 32);
            ldsm_x4(aL[0], smb + SQL + a_off[0] + kk * 32);
            ldsm_x4(aH[1], smb + SQH + a_off[1] + kk * 32);
            ldsm_x4(aL[1], smb + SQL + a_off[1] + kk * 32);
            #pragma unroll
            for (int p = 0; p < 2; ++p) {
                const uint32_t toff = (uint32_t)(p * 16 * PAD + kk * 16) * 2;
                uint32_t bH[4], bL[4];
                ldsm_x4(bH, kh + kb4_off + toff);
                ldsm_x4(bL, kl + kb4_off + toff);
                #pragma unroll
                for (int mt = 0; mt < 2; ++mt) {
                    mma16816(c[mt][2 * p + 0], aH[mt], bH + 0);
                    mma16816(c[mt][2 * p + 1], aH[mt], bH + 2);
                    mma16816(c[mt][2 * p + 0], aH[mt], bL + 0);
                    mma16816(c[mt][2 * p + 1], aH[mt], bL + 2);
                    mma16816(c[mt][2 * p + 0], aL[mt], bH + 0);
                    mma16816(c[mt][2 * p + 1], aL[mt], bH + 2);
                }
            }
        }

        // ---- two 16-key halves: online softmax -> PV ----
        #pragma unroll
        for (int h = 0; h < 2; ++h) {
            // fold mask + tile max per row-group
            float tm[4] = {-1e30f, -1e30f, -1e30f, -1e30f};
            #pragma unroll
            for (int mt = 0; mt < 2; ++mt)
                #pragma unroll
                for (int j = 0; j < 2; ++j) {
                    const int n = 2 * h + j;
                    c[mt][n][0] += mA[mt][n].x;  c[mt][n][1] += mA[mt][n].y;
                    c[mt][n][2] += mB[mt][n].x;  c[mt][n][3] += mB[mt][n].y;
                    tm[2 * mt + 0] = fmaxf(tm[2 * mt + 0], fmaxf(c[mt][n][0], c[mt][n][1]));
                    tm[2 * mt + 1] = fmaxf(tm[2 * mt + 1], fmaxf(c[mt][n][2], c[mt][n][3]));
                }
            bool newmax = false;
            #pragma unroll
            for (int rg = 0; rg < 4; ++rg) {
                tm[rg] = fmaxf(tm[rg], __shfl_xor_sync(0xffffffffu, tm[rg], 1));
                tm[rg] = fmaxf(tm[rg], __shfl_xor_sync(0xffffffffu, tm[rg], 2));
                newmax |= (tm[rg] > M[rg]);
            }
            if (__any_sync(0xffffffffu, newmax)) {
                float sc[4];
                #pragma unroll
                for (int rg = 0; rg < 4; ++rg) {
                    const float Mn = fmaxf(M[rg], tm[rg]);
                    sc[rg] = __expf(M[rg] - Mn);
                    M[rg] = Mn;
                    Z[rg] *= sc[rg];
                }
                #pragma unroll
                for (int mt = 0; mt < 2; ++mt)
                    #pragma unroll
                    for (int n = 0; n < 16; ++n) {
                        o[mt][n][0] *= sc[2 * mt + 0]; o[mt][n][1] *= sc[2 * mt + 0];
                        o[mt][n][2] *= sc[2 * mt + 1]; o[mt][n][3] *= sc[2 * mt + 1];
                    }
            }
            // P' = exp(s - M) in fp16; Z accumulate
            uint32_t ph[2][4];
            #pragma unroll
            for (int mt = 0; mt < 2; ++mt) {
                const float* c0 = c[mt][2 * h + 0];
                const float* c1 = c[mt][2 * h + 1];
                float e0 = __expf(c0[0] - M[2 * mt]),     e1 = __expf(c0[1] - M[2 * mt]);
                float e2 = __expf(c0[2] - M[2 * mt + 1]), e3 = __expf(c0[3] - M[2 * mt + 1]);
                float f0 = __expf(c1[0] - M[2 * mt]),     f1 = __expf(c1[1] - M[2 * mt]);
                float f2 = __expf(c1[2] - M[2 * mt + 1]), f3 = __expf(c1[3] - M[2 * mt + 1]);
                Z[2 * mt + 0] += (e0 + e1) + (f0 + f1);
                Z[2 * mt + 1] += (e2 + e3) + (f2 + f3);
                ph[mt][0] = pack2h(__float2half_rn(e0), __float2half_rn(e1));
                ph[mt][1] = pack2h(__float2half_rn(e2), __float2half_rn(e3));
                ph[mt][2] = pack2h(__float2half_rn(f0), __float2half_rn(f1));
                ph[mt][3] = pack2h(__float2half_rn(f2), __float2half_rn(f3));
            }
            // PV over this half's 16 keys
            #pragma unroll
            for (int dp = 0; dp < 8; ++dp) {
                const uint32_t toff = (uint32_t)(h * 16 * PAD + dp * 16) * 2;
                uint32_t vf[4];
                ldsm_x4_t(vf, vv + vb4_off + toff);
                #pragma unroll
                for (int mt = 0; mt < 2; ++mt) {
                    mma16816(o[mt][2 * dp + 0], ph[mt], vf + 0);
                    mma16816(o[mt][2 * dp + 1], ph[mt], vf + 2);
                }
            }
        }
    }

    // ---- quad-reduce Z; LayerNorm per row-group; write ----
    #pragma unroll
    for (int rg = 0; rg < 4; ++rg) {
        Z[rg] += __shfl_xor_sync(0xffffffffu, Z[rg], 1);
        Z[rg] += __shfl_xor_sync(0xffffffffu, Z[rg], 2);
    }
    #pragma unroll
    for (int rg = 0; rg < 4; ++rg) {
        const int mt = rg >> 1, ih = (rg & 1) * 2;
        const float zi = 1.0f / Z[rg];
        float s1 = 0.f, s2 = 0.f;
        #pragma unroll
        for (int n = 0; n < 16; ++n) {
            float x0 = o[mt][n][ih + 0] * zi, x1 = o[mt][n][ih + 1] * zi;
            s1 += x0 + x1;
            s2 += x0 * x0 + x1 * x1;
        }
        s1 += __shfl_xor_sync(0xffffffffu, s1, 1); s1 += __shfl_xor_sync(0xffffffffu, s1, 2);
        s2 += __shfl_xor_sync(0xffffffffu, s2, 1); s2 += __shfl_xor_sync(0xffffffffu, s2, 2);
        const float mu = s1 * (1.0f / 128.0f);
        const float va = fmaxf(s2 * (1.0f / 128.0f) - mu * mu, 0.0f);
        const float rs = rsqrtf(va + 1e-5f);
        float* orow = OUT + ((size_t)(b * LSEQ + q0 + 32 * w + 16 * mt + 8 * (rg & 1) + qr)) * DHEAD;
        #pragma unroll
        for (int n = 0; n < 16; ++n) {
            const int cb = 8 * n + qc2;
            const float2 g2 = *reinterpret_cast<const float2*>(GAMMA + cb);
            const float2 b2 = *reinterpret_cast<const float2*>(BETA + cb);
            float2 y;
            y.x = (o[mt][n][ih + 0] * zi - mu) * rs * g2.x + b2.x;
            y.y = (o[mt][n][ih + 1] * zi - mu) * rs * g2.y + b2.y;
            *reinterpret_cast<float2*>(orow + cb) = y;
        }
    }
}

extern "C" void kernel_launch(void* const* d_in, const int* in_sizes, int n_in,
                              void* d_out, int out_size) {
    (void)in_sizes; (void)n_in; (void)out_size;
    const float* q     = (const float*)d_in[0];
    const float* k     = (const float*)d_in[1];
    const float* v     = (const float*)d_in[2];
    const float* mask  = (const float*)d_in[3];
    const float* gamma = (const float*)d_in[4];
    const float* beta  = (const float*)d_in[5];
    float* out = (float*)d_out;

    cudaFuncSetAttribute(fmha_ln_hmma, cudaFuncAttributeMaxDynamicSharedMemorySize, SMEM_BYTES);

    const int total_f4 = BATCH * LSEQ * DHEAD / 4;
    prep_split<<<total_f4 / 256, 256>>>(q, k, v);
    fmha_ln_hmma<<<dim3(LSEQ / TQ, BATCH), THREADS, SMEM_BYTES>>>(mask, gamma, beta, out);
}

// round 16
// speedup vs baseline: 1.4675x; 1.4675x over previous
#include <cuda_runtime.h>
#include <cuda_fp16.h>
#include <stdint.h>

// R16 = R14 (best: 254.3us) with unified S-phase A-loads (A ldmatrix once per
// kk covering all 4 p-groups, pass-major) — removes the per-half A reload.
// Keeps: fp16 hi/lo QK 3-pass, single-pass fp16 PV, online softmax with
// half-tile pipeline, double-buffered cp.async staging.

static constexpr int BATCH = 16;
static constexpr int LSEQ  = 2048;
static constexpr int DHEAD = 128;
static constexpr int TQ    = 128;
static constexpr int TKN   = 64;
static constexpr int NKT   = LSEQ / TKN;   // 32

static constexpr int PAD   = 136;
static constexpr int QT_BYTES = TQ  * PAD * 2;
static constexpr int KT_BYTES = TKN * PAD * 2;
static constexpr int SQH = 0;
static constexpr int SQL = QT_BYTES;
static constexpr int SBUF0 = 2 * QT_BYTES;
static constexpr int BUF_STRIDE = 3 * KT_BYTES;          // KH, KL, V
static constexpr int OKH = 0, OKL = KT_BYTES, OV = 2 * KT_BYTES;
static constexpr int SMEM_BYTES = SBUF0 + 2 * BUF_STRIDE;  // 174080

__device__ __align__(16) __half g_qh[(size_t)BATCH * LSEQ * DHEAD];
__device__ __align__(16) __half g_ql[(size_t)BATCH * LSEQ * DHEAD];
__device__ __align__(16) __half g_kh[(size_t)BATCH * LSEQ * DHEAD];
__device__ __align__(16) __half g_kl[(size_t)BATCH * LSEQ * DHEAD];
__device__ __align__(16) __half g_v [(size_t)BATCH * LSEQ * DHEAD];

// ---------------- helpers ----------------
__device__ __forceinline__ uint32_t smem_u32(const void* p) {
    uint32_t a;
    asm("{ .reg .u64 t; cvta.to.shared.u64 t, %1; cvt.u32.u64 %0, t; }" : "=r"(a) : "l"(p));
    return a;
}
__device__ __forceinline__ uint32_t pack2h(__half a, __half b) {
    return (uint32_t)__half_as_ushort(a) | ((uint32_t)__half_as_ushort(b) << 16);
}
__device__ __forceinline__ void ldsm_x4(uint32_t* r, uint32_t addr) {
    asm volatile("ldmatrix.sync.aligned.m8n8.x4.shared.b16 {%0,%1,%2,%3}, [%4];"
                 : "=r"(r[0]), "=r"(r[1]), "=r"(r[2]), "=r"(r[3]) : "r"(addr));
}
__device__ __forceinline__ void ldsm_x4_t(uint32_t* r, uint32_t addr) {
    asm volatile("ldmatrix.sync.aligned.m8n8.x4.trans.shared.b16 {%0,%1,%2,%3}, [%4];"
                 : "=r"(r[0]), "=r"(r[1]), "=r"(r[2]), "=r"(r[3]) : "r"(addr));
}
__device__ __forceinline__ void mma16816(float* d, const uint32_t* a, const uint32_t* b) {
    asm volatile("mma.sync.aligned.m16n8k16.row.col.f32.f16.f16.f32 "
                 "{%0,%1,%2,%3}, {%4,%5,%6,%7}, {%8,%9}, {%0,%1,%2,%3};"
                 : "+f"(d[0]), "+f"(d[1]), "+f"(d[2]), "+f"(d[3])
                 : "r"(a[0]), "r"(a[1]), "r"(a[2]), "r"(a[3]), "r"(b[0]), "r"(b[1]));
}
__device__ __forceinline__ void cp16(uint32_t dst, const void* src) {
    asm volatile("cp.async.cg.shared.global [%0], [%1], 16;" :: "r"(dst), "l"(src));
}
#define CP_COMMIT() asm volatile("cp.async.commit_group;" ::: "memory")

__device__ __forceinline__ void stage64(uint32_t dstb, const __half* __restrict__ g, int tid) {
    #pragma unroll
    for (int i = 0; i < 4; ++i) {
        int idx = tid + i * 256;
        int row = idx >> 4, c = idx & 15;
        cp16(dstb + row * (PAD * 2) + c * 16, g + row * DHEAD + c * 8);
    }
}
__device__ __forceinline__ void stage128(uint32_t dstb, const __half* __restrict__ g, int tid) {
    #pragma unroll
    for (int i = 0; i < 8; ++i) {
        int idx = tid + i * 256;
        int row = idx >> 4, c = idx & 15;
        cp16(dstb + row * (PAD * 2) + c * 16, g + row * DHEAD + c * 8);
    }
}

// -------- prep: fp32 -> fp16 hi/lo (Q,K) and fp16 (V) --------
__device__ __forceinline__ void split4h(float4 f, __half* hi, __half* lo, size_t i4) {
    __half h0 = __float2half_rn(f.x), h1 = __float2half_rn(f.y);
    __half h2 = __float2half_rn(f.z), h3 = __float2half_rn(f.w);
    *reinterpret_cast<uint2*>(hi + 4 * i4) = make_uint2(pack2h(h0, h1), pack2h(h2, h3));
    *reinterpret_cast<uint2*>(lo + 4 * i4) = make_uint2(
        pack2h(__float2half_rn(f.x - __half2float(h0)), __float2half_rn(f.y - __half2float(h1))),
        pack2h(__float2half_rn(f.z - __half2float(h2)), __float2half_rn(f.w - __half2float(h3))));
}
__global__ void prep_split(const float* __restrict__ q, const float* __restrict__ k,
                           const float* __restrict__ v) {
    size_t i = (size_t)blockIdx.x * blockDim.x + threadIdx.x;
    split4h(reinterpret_cast<const float4*>(q)[i], g_qh, g_ql, i);
    split4h(reinterpret_cast<const float4*>(k)[i], g_kh, g_kl, i);
    float4 fv = reinterpret_cast<const float4*>(v)[i];
    *reinterpret_cast<uint2*>(g_v + 4 * i) = make_uint2(
        pack2h(__float2half_rn(fv.x), __float2half_rn(fv.y)),
        pack2h(__float2half_rn(fv.z), __float2half_rn(fv.w)));
}

// -------- fused attention + layernorm --------
__global__ void __launch_bounds__(256, 1)
fmha_ln_hmma(const float* __restrict__ MASK, const float* __restrict__ GAMMA,
             const float* __restrict__ BETA, float* __restrict__ OUT) {
    extern __shared__ char sm[];
    const int tid = threadIdx.x;
    const int w   = tid >> 5;
    const int l   = tid & 31;
    const int b   = blockIdx.y;
    const int q0  = blockIdx.x * TQ;

    const int qr  = l >> 2;
    const int qc2 = (l & 3) * 2;
    const int r1  = 16 * w + qr;

    const uint32_t smb = smem_u32(sm);

    const int lr = l & 7, g = l >> 3;
    const int a_row = 16 * w + lr + ((g & 1) << 3);
    const uint32_t a_off   = (uint32_t)(a_row * PAD + ((g >> 1) << 3)) * 2;
    const uint32_t kb4_off = (uint32_t)((lr + ((g >> 1) << 3)) * PAD + ((g & 1) << 3)) * 2;
    const uint32_t vb4_off = (uint32_t)((lr + ((g & 1) << 3)) * PAD + ((g >> 1) << 3)) * 2;

    const size_t qgbase = ((size_t)(b * LSEQ + q0)) * DHEAD;
    const size_t kvbase = ((size_t)b * LSEQ) * DHEAD;

    stage128(smb + SQH, g_qh + qgbase, tid);
    stage128(smb + SQL, g_ql + qgbase, tid);
    {
        const uint32_t d0 = smb + SBUF0;
        stage64(d0 + OKH, g_kh + kvbase, tid);
        stage64(d0 + OKL, g_kl + kvbase, tid);
        stage64(d0 + OV,  g_v  + kvbase, tid);
    }
    CP_COMMIT();

    float o[16][4];
    #pragma unroll
    for (int n = 0; n < 16; ++n) { o[n][0] = o[n][1] = o[n][2] = o[n][3] = 0.f; }
    float Z1 = 0.f, Z2 = 0.f;
    float M1 = -1e30f, M2 = -1e30f;

    const float* mrow1 = MASK + (size_t)(q0 + r1) * LSEQ;
    const float* mrow2 = mrow1 + 8 * LSEQ;

    #pragma unroll 1
    for (int kt = 0; kt < NKT; ++kt) {
        if (kt + 1 < NKT) {
            const uint32_t dn = smb + SBUF0 + ((kt + 1) & 1) * BUF_STRIDE;
            const size_t tn = kvbase + (size_t)(kt + 1) * TKN * DHEAD;
            stage64(dn + OKH, g_kh + tn, tid);
            stage64(dn + OKL, g_kl + tn, tid);
            stage64(dn + OV,  g_v  + tn, tid);
            CP_COMMIT();
            asm volatile("cp.async.wait_group 1;" ::: "memory");
        } else {
            asm volatile("cp.async.wait_group 0;" ::: "memory");
        }
        __syncthreads();

        const uint32_t bufb = smb + SBUF0 + (kt & 1) * BUF_STRIDE;
        const uint32_t kh = bufb + OKH, kl = bufb + OKL;
        const uint32_t vv = bufb + OV;

        // ---- prefetch mask fragments (whole tile) ----
        float2 m1r[8], m2r[8];
        #pragma unroll
        for (int n = 0; n < 8; ++n) {
            const int cb = kt * TKN + 8 * n + qc2;
            m1r[n] = *reinterpret_cast<const float2*>(mrow1 + cb);
            m2r[n] = *reinterpret_cast<const float2*>(mrow2 + cb);
        }

        // ---- S = Qhi*Khi + Qhi*Klo + Qlo*Khi (A loaded ONCE per kk, pass-major) ----
        float c[8][4];
        #pragma unroll
        for (int n = 0; n < 8; ++n) { c[n][0] = c[n][1] = c[n][2] = c[n][3] = 0.f; }

        #pragma unroll
        for (int kk = 0; kk < 8; ++kk) {
            uint32_t aH[4], aL[4];
            ldsm_x4(aH, smb + SQH + a_off + kk * 32);
            ldsm_x4(aL, smb + SQL + a_off + kk * 32);
            uint32_t bH[4][4], bL[4][4];
            #pragma unroll
            for (int p = 0; p < 4; ++p) {
                const uint32_t toff = (uint32_t)(p * 16 * PAD + kk * 16) * 2;
                ldsm_x4(bH[p], kh + kb4_off + toff);
                ldsm_x4(bL[p], kl + kb4_off + toff);
            }
            #pragma unroll
            for (int p = 0; p < 4; ++p) {
                mma16816(c[2 * p + 0], aH, bH[p] + 0);
                mma16816(c[2 * p + 1], aH, bH[p] + 2);
            }
            #pragma unroll
            for (int p = 0; p < 4; ++p) {
                mma16816(c[2 * p + 0], aH, bL[p] + 0);
                mma16816(c[2 * p + 1], aH, bL[p] + 2);
            }
            #pragma unroll
            for (int p = 0; p < 4; ++p) {
                mma16816(c[2 * p + 0], aL, bH[p] + 0);
                mma16816(c[2 * p + 1], aL, bH[p] + 2);
            }
        }

        // ---- two halves: softmax(h) overlaps tensor drain ----
        #pragma unroll
        for (int h = 0; h < 2; ++h) {
            const int nb = 4 * h;
            float m1t = -1e30f, m2t = -1e30f;
            #pragma unroll
            for (int n = 0; n < 4; ++n) {
                c[nb + n][0] += m1r[nb + n].x;  c[nb + n][1] += m1r[nb + n].y;
                c[nb + n][2] += m2r[nb + n].x;  c[nb + n][3] += m2r[nb + n].y;
                m1t = fmaxf(m1t, fmaxf(c[nb + n][0], c[nb + n][1]));
                m2t = fmaxf(m2t, fmaxf(c[nb + n][2], c[nb + n][3]));
            }
            m1t = fmaxf(m1t, __shfl_xor_sync(0xffffffffu, m1t, 1));
            m1t = fmaxf(m1t, __shfl_xor_sync(0xffffffffu, m1t, 2));
            m2t = fmaxf(m2t, __shfl_xor_sync(0xffffffffu, m2t, 1));
            m2t = fmaxf(m2t, __shfl_xor_sync(0xffffffffu, m2t, 2));
            const bool newmax = (m1t > M1) || (m2t > M2);
            if (__any_sync(0xffffffffu, newmax)) {
                const float Mn1 = fmaxf(M1, m1t);
                const float Mn2 = fmaxf(M2, m2t);
                const float sc1 = __expf(M1 - Mn1);
                const float sc2 = __expf(M2 - Mn2);
                M1 = Mn1; M2 = Mn2;
                Z1 *= sc1; Z2 *= sc2;
                #pragma unroll
                for (int n = 0; n < 16; ++n) {
                    o[n][0] *= sc1; o[n][1] *= sc1;
                    o[n][2] *= sc2; o[n][3] *= sc2;
                }
            }
            uint32_t ph[2][4];
            #pragma unroll
            for (int s = 0; s < 2; ++s) {
                const float* c0 = c[nb + 2 * s + 0];
                const float* c1 = c[nb + 2 * s + 1];
                float e0 = __expf(c0[0] - M1), e1 = __expf(c0[1] - M1);
                float e2 = __expf(c0[2] - M2), e3 = __expf(c0[3] - M2);
                float f0 = __expf(c1[0] - M1), f1 = __expf(c1[1] - M1);
                float f2 = __expf(c1[2] - M2), f3 = __expf(c1[3] - M2);
                Z1 += (e0 + e1) + (f0 + f1);
                Z2 += (e2 + e3) + (f2 + f3);
                ph[s][0] = pack2h(__float2half_rn(e0), __float2half_rn(e1));
                ph[s][1] = pack2h(__float2half_rn(e2), __float2half_rn(e3));
                ph[s][2] = pack2h(__float2half_rn(f0), __float2half_rn(f1));
                ph[s][3] = pack2h(__float2half_rn(f2), __float2half_rn(f3));
            }
            #pragma unroll
            for (int s = 0; s < 2; ++s) {
                const int sg = 2 * h + s;
                #pragma unroll
                for (int dp = 0; dp < 8; ++dp) {
                    const uint32_t toff = (uint32_t)(sg * 16 * PAD + dp * 16) * 2;
                    uint32_t vf[4];
                    ldsm_x4_t(vf, vv + vb4_off + toff);
                    mma16816(o[2 * dp + 0], ph[s], vf + 0);
                    mma16816(o[2 * dp + 1], ph[s], vf + 2);
                }
            }
        }
        __syncthreads();
    }

    // ---- quad-reduce Z; LayerNorm; write ----
    Z1 += __shfl_xor_sync(0xffffffffu, Z1, 1);
    Z1 += __shfl_xor_sync(0xffffffffu, Z1, 2);
    Z2 += __shfl_xor_sync(0xffffffffu, Z2, 1);
    Z2 += __shfl_xor_sync(0xffffffffu, Z2, 2);
    const float zi1 = 1.0f / Z1, zi2 = 1.0f / Z2;

    float s1a = 0.f, s1b = 0.f, s2a = 0.f, s2b = 0.f;
    #pragma unroll
    for (int n = 0; n < 16; ++n) {
        float x0 = o[n][0] * zi1, x1 = o[n][1] * zi1;
        float x2 = o[n][2] * zi2, x3 = o[n][3] * zi2;
        s1a += x0 + x1;  s1b += x0 * x0 + x1 * x1;
        s2a += x2 + x3;  s2b += x2 * x2 + x3 * x3;
    }
    s1a += __shfl_xor_sync(0xffffffffu, s1a, 1); s1a += __shfl_xor_sync(0xffffffffu, s1a, 2);
    s1b += __shfl_xor_sync(0xffffffffu, s1b, 1); s1b += __shfl_xor_sync(0xffffffffu, s1b, 2);
    s2a += __shfl_xor_sync(0xffffffffu, s2a, 1); s2a += __shfl_xor_sync(0xffffffffu, s2a, 2);
    s2b += __shfl_xor_sync(0xffffffffu, s2b, 1); s2b += __shfl_xor_sync(0xffffffffu, s2b, 2);

    const float mu1 = s1a * (1.0f / 128.0f);
    const float v1  = fmaxf(s1b * (1.0f / 128.0f) - mu1 * mu1, 0.0f);
    const float rs1 = rsqrtf(v1 + 1e-5f);
    const float mu2 = s2a * (1.0f / 128.0f);
    const float v2  = fmaxf(s2b * (1.0f / 128.0f) - mu2 * mu2, 0.0f);
    const float rs2 = rsqrtf(v2 + 1e-5f);

    float* orow1 = OUT + ((size_t)(b * LSEQ + q0 + r1)) * DHEAD;
    float* orow2 = orow1 + 8 * DHEAD;
    #pragma unroll
    for (int n = 0; n < 16; ++n) {
        const int cb = 8 * n + qc2;
        const float2 g2 = *reinterpret_cast<const float2*>(GAMMA + cb);
        const float2 b2 = *reinterpret_cast<const float2*>(BETA + cb);
        float2 y1, y2;
        y1.x = (o[n][0] * zi1 - mu1) * rs1 * g2.x + b2.x;
        y1.y = (o[n][1] * zi1 - mu1) * rs1 * g2.y + b2.y;
        y2.x = (o[n][2] * zi2 - mu2) * rs2 * g2.x + b2.x;
        y2.y = (o[n][3] * zi2 - mu2) * rs2 * g2.y + b2.y;
        *reinterpret_cast<float2*>(orow1 + cb) = y1;
        *reinterpret_cast<float2*>(orow2 + cb) = y2;
    }
}

extern "C" void kernel_launch(void* const* d_in, const int* in_sizes, int n_in,
                              void* d_out, int out_size) {
    (void)in_sizes; (void)n_in; (void)out_size;
    const float* q     = (const float*)d_in[0];
    const float* k     = (const float*)d_in[1];
    const float* v     = (const float*)d_in[2];
    const float* mask  = (const float*)d_in[3];
    const float* gamma = (const float*)d_in[4];
    const float* beta  = (const float*)d_in[5];
    float* out = (float*)d_out;

    cudaFuncSetAttribute(fmha_ln_hmma, cudaFuncAttributeMaxDynamicSharedMemorySize, SMEM_BYTES);

    const int total_f4 = BATCH * LSEQ * DHEAD / 4;
    prep_split<<<total_f4 / 256, 256>>>(q, k, v);
    fmha_ln_hmma<<<dim3(LSEQ / TQ, BATCH), 256, SMEM_BYTES>>>(mask, gamma, beta, out);
}

// round 17
// speedup vs baseline: 1.5724x; 1.0715x over previous
#include <cuda_runtime.h>
#include <cuda_fp16.h>
#include <stdint.h>

// R17: fat warps (8 warps x 32 rows, TQ=256, TKN=32) -> 0.31 x4-LDSM per MMA,
// WITH the double-buffered cp.async pipeline kept (R15's fatal omission) and
// 2 warps/SMSP (256 threads). Numerics identical to R15/R16 (rel_err 2.1e-4).

static constexpr int BATCH = 16;
static constexpr int LSEQ  = 2048;
static constexpr int DHEAD = 128;
static constexpr int TQ    = 256;   // 8 warps x 32 rows
static constexpr int TKN   = 32;
static constexpr int NKT   = LSEQ / TKN;   // 64
static constexpr int THREADS = 256;

static constexpr int PAD   = 136;
static constexpr int QT_BYTES = TQ  * PAD * 2;   // 69632 per Q tile (hi or lo)
static constexpr int KT_BYTES = TKN * PAD * 2;   // 8704
static constexpr int SQH = 0;
static constexpr int SQL = QT_BYTES;
static constexpr int SBUF0 = 2 * QT_BYTES;               // 139264
static constexpr int BUF_STRIDE = 3 * KT_BYTES;          // 26112 (KH, KL, V)
static constexpr int OKH = 0, OKL = KT_BYTES, OV = 2 * KT_BYTES;
static constexpr int SMEM_BYTES = SBUF0 + 2 * BUF_STRIDE;  // 191488

__device__ __align__(16) __half g_qh[(size_t)BATCH * LSEQ * DHEAD];
__device__ __align__(16) __half g_ql[(size_t)BATCH * LSEQ * DHEAD];
__device__ __align__(16) __half g_kh[(size_t)BATCH * LSEQ * DHEAD];
__device__ __align__(16) __half g_kl[(size_t)BATCH * LSEQ * DHEAD];
__device__ __align__(16) __half g_v [(size_t)BATCH * LSEQ * DHEAD];

// ---------------- helpers ----------------
__device__ __forceinline__ uint32_t smem_u32(const void* p) {
    uint32_t a;
    asm("{ .reg .u64 t; cvta.to.shared.u64 t, %1; cvt.u32.u64 %0, t; }" : "=r"(a) : "l"(p));
    return a;
}
__device__ __forceinline__ uint32_t pack2h(__half a, __half b) {
    return (uint32_t)__half_as_ushort(a) | ((uint32_t)__half_as_ushort(b) << 16);
}
__device__ __forceinline__ void ldsm_x4(uint32_t* r, uint32_t addr) {
    asm volatile("ldmatrix.sync.aligned.m8n8.x4.shared.b16 {%0,%1,%2,%3}, [%4];"
                 : "=r"(r[0]), "=r"(r[1]), "=r"(r[2]), "=r"(r[3]) : "r"(addr));
}
__device__ __forceinline__ void ldsm_x4_t(uint32_t* r, uint32_t addr) {
    asm volatile("ldmatrix.sync.aligned.m8n8.x4.trans.shared.b16 {%0,%1,%2,%3}, [%4];"
                 : "=r"(r[0]), "=r"(r[1]), "=r"(r[2]), "=r"(r[3]) : "r"(addr));
}
__device__ __forceinline__ void mma16816(float* d, const uint32_t* a, const uint32_t* b) {
    asm volatile("mma.sync.aligned.m16n8k16.row.col.f32.f16.f16.f32 "
                 "{%0,%1,%2,%3}, {%4,%5,%6,%7}, {%8,%9}, {%0,%1,%2,%3};"
                 : "+f"(d[0]), "+f"(d[1]), "+f"(d[2]), "+f"(d[3])
                 : "r"(a[0]), "r"(a[1]), "r"(a[2]), "r"(a[3]), "r"(b[0]), "r"(b[1]));
}
__device__ __forceinline__ void cp16(uint32_t dst, const void* src) {
    asm volatile("cp.async.cg.shared.global [%0], [%1], 16;" :: "r"(dst), "l"(src));
}
#define CP_COMMIT() asm volatile("cp.async.commit_group;" ::: "memory")

// 32-row tile, 256 threads: 512 chunks -> 2 each
__device__ __forceinline__ void stage32(uint32_t dstb, const __half* __restrict__ g, int tid) {
    #pragma unroll
    for (int i = 0; i < 2; ++i) {
        int idx = tid + i * THREADS;
        int row = idx >> 4, c = idx & 15;
        cp16(dstb + row * (PAD * 2) + c * 16, g + row * DHEAD + c * 8);
    }
}
// 256-row tile: 4096 chunks -> 16 each
__device__ __forceinline__ void stage256q(uint32_t dstb, const __half* __restrict__ g, int tid) {
    #pragma unroll
    for (int i = 0; i < 16; ++i) {
        int idx = tid + i * THREADS;
        int row = idx >> 4, c = idx & 15;
        cp16(dstb + row * (PAD * 2) + c * 16, g + row * DHEAD + c * 8);
    }
}

// -------- prep: fp32 -> fp16 hi/lo (Q,K) and fp16 (V) --------
__device__ __forceinline__ void split4h(float4 f, __half* hi, __half* lo, size_t i4) {
    __half h0 = __float2half_rn(f.x), h1 = __float2half_rn(f.y);
    __half h2 = __float2half_rn(f.z), h3 = __float2half_rn(f.w);
    *reinterpret_cast<uint2*>(hi + 4 * i4) = make_uint2(pack2h(h0, h1), pack2h(h2, h3));
    *reinterpret_cast<uint2*>(lo + 4 * i4) = make_uint2(
        pack2h(__float2half_rn(f.x - __half2float(h0)), __float2half_rn(f.y - __half2float(h1))),
        pack2h(__float2half_rn(f.z - __half2float(h2)), __float2half_rn(f.w - __half2float(h3))));
}
__global__ void prep_split(const float* __restrict__ q, const float* __restrict__ k,
                           const float* __restrict__ v) {
    size_t i = (size_t)blockIdx.x * blockDim.x + threadIdx.x;
    split4h(reinterpret_cast<const float4*>(q)[i], g_qh, g_ql, i);
    split4h(reinterpret_cast<const float4*>(k)[i], g_kh, g_kl, i);
    float4 fv = reinterpret_cast<const float4*>(v)[i];
    *reinterpret_cast<uint2*>(g_v + 4 * i) = make_uint2(
        pack2h(__float2half_rn(fv.x), __float2half_rn(fv.y)),
        pack2h(__float2half_rn(fv.z), __float2half_rn(fv.w)));
}

// -------- fused attention + layernorm --------
__global__ void __launch_bounds__(THREADS, 1)
fmha_ln_hmma(const float* __restrict__ MASK, const float* __restrict__ GAMMA,
             const float* __restrict__ BETA, float* __restrict__ OUT) {
    extern __shared__ char sm[];
    const int tid = threadIdx.x;
    const int w   = tid >> 5;          // 0..7, owns rows 32w..32w+31
    const int l   = tid & 31;
    const int b   = blockIdx.y;
    const int q0  = blockIdx.x * TQ;

    const int qr  = l >> 2;
    const int qc2 = (l & 3) * 2;

    const uint32_t smb = smem_u32(sm);
    const int lr = l & 7, g = l >> 3;

    uint32_t a_off[2];
    #pragma unroll
    for (int mt = 0; mt < 2; ++mt)
        a_off[mt] = (uint32_t)((32 * w + 16 * mt + lr + ((g & 1) << 3)) * PAD + ((g >> 1) << 3)) * 2;
    const uint32_t kb4_off = (uint32_t)((lr + ((g >> 1) << 3)) * PAD + ((g & 1) << 3)) * 2;
    const uint32_t vb4_off = (uint32_t)((lr + ((g & 1) << 3)) * PAD + ((g >> 1) << 3)) * 2;

    const size_t qgbase = ((size_t)(b * LSEQ + q0)) * DHEAD;
    const size_t kvbase = ((size_t)b * LSEQ) * DHEAD;

    stage256q(smb + SQH, g_qh + qgbase, tid);
    stage256q(smb + SQL, g_ql + qgbase, tid);
    {
        const uint32_t d0 = smb + SBUF0;
        stage32(d0 + OKH, g_kh + kvbase, tid);
        stage32(d0 + OKL, g_kl + kvbase, tid);
        stage32(d0 + OV,  g_v  + kvbase, tid);
    }
    CP_COMMIT();

    float o[2][16][4];
    #pragma unroll
    for (int mt = 0; mt < 2; ++mt)
        #pragma unroll
        for (int n = 0; n < 16; ++n) { o[mt][n][0] = o[mt][n][1] = o[mt][n][2] = o[mt][n][3] = 0.f; }
    float Z[4] = {0.f, 0.f, 0.f, 0.f};
    float M[4] = {-1e30f, -1e30f, -1e30f, -1e30f};   // rg = 2*mt + hiRow

    const float* mrL[2];
    #pragma unroll
    for (int mt = 0; mt < 2; ++mt)
        mrL[mt] = MASK + (size_t)(q0 + 32 * w + 16 * mt + qr) * LSEQ;

    #pragma unroll 1
    for (int kt = 0; kt < NKT; ++kt) {
        if (kt + 1 < NKT) {
            const uint32_t dn = smb + SBUF0 + ((kt + 1) & 1) * BUF_STRIDE;
            const size_t tn = kvbase + (size_t)(kt + 1) * TKN * DHEAD;
            stage32(dn + OKH, g_kh + tn, tid);
            stage32(dn + OKL, g_kl + tn, tid);
            stage32(dn + OV,  g_v  + tn, tid);
            CP_COMMIT();
            asm volatile("cp.async.wait_group 1;" ::: "memory");
        } else {
            asm volatile("cp.async.wait_group 0;" ::: "memory");
        }
        __syncthreads();

        const uint32_t bufb = smb + SBUF0 + (kt & 1) * BUF_STRIDE;
        const uint32_t kh = bufb + OKH, kl = bufb + OKL;
        const uint32_t vv = bufb + OV;

        // ---- mask prefetch ----
        float2 mA[2][4], mB[2][4];
        #pragma unroll
        for (int mt = 0; mt < 2; ++mt)
            #pragma unroll
            for (int n = 0; n < 4; ++n) {
                const int cb = kt * TKN + 8 * n + qc2;
                mA[mt][n] = *reinterpret_cast<const float2*>(mrL[mt] + cb);
                mB[mt][n] = *reinterpret_cast<const float2*>(mrL[mt] + 8 * LSEQ + cb);
            }

        // ---- S = Qhi*Khi + Qhi*Klo + Qlo*Khi ----
        float c[2][4][4];
        #pragma unroll
        for (int mt = 0; mt < 2; ++mt)
            #pragma unroll
            for (int n = 0; n < 4; ++n) { c[mt][n][0] = c[mt][n][1] = c[mt][n][2] = c[mt][n][3] = 0.f; }

        #pragma unroll
        for (int kk = 0; kk < 8; ++kk) {
            uint32_t aH[2][4], aL[2][4];
            ldsm_x4(aH[0], smb + SQH + a_off[0] + kk * 32);
            ldsm_x4(aL[0], smb + SQL + a_off[0] + kk * 32);
            ldsm_x4(aH[1], smb + SQH + a_off[1] + kk * 32);
            ldsm_x4(aL[1], smb + SQL + a_off[1] + kk * 32);
            #pragma unroll
            for (int p = 0; p < 2; ++p) {
                const uint32_t toff = (uint32_t)(p * 16 * PAD + kk * 16) * 2;
                uint32_t bH[4], bL[4];
                ldsm_x4(bH, kh + kb4_off + toff);
                ldsm_x4(bL, kl + kb4_off + toff);
                #pragma unroll
                for (int mt = 0; mt < 2; ++mt) {
                    mma16816(c[mt][2 * p + 0], aH[mt], bH + 0);
                    mma16816(c[mt][2 * p + 1], aH[mt], bH + 2);
                    mma16816(c[mt][2 * p + 0], aH[mt], bL + 0);
                    mma16816(c[mt][2 * p + 1], aH[mt], bL + 2);
                    mma16816(c[mt][2 * p + 0], aL[mt], bH + 0);
                    mma16816(c[mt][2 * p + 1], aL[mt], bH + 2);
                }
            }
        }

        // ---- two 16-key halves: online softmax -> PV ----
        #pragma unroll
        for (int h = 0; h < 2; ++h) {
            float tm[4] = {-1e30f, -1e30f, -1e30f, -1e30f};
            #pragma unroll
            for (int mt = 0; mt < 2; ++mt)
                #pragma unroll
                for (int j = 0; j < 2; ++j) {
                    const int n = 2 * h + j;
                    c[mt][n][0] += mA[mt][n].x;  c[mt][n][1] += mA[mt][n].y;
                    c[mt][n][2] += mB[mt][n].x;  c[mt][n][3] += mB[mt][n].y;
                    tm[2 * mt + 0] = fmaxf(tm[2 * mt + 0], fmaxf(c[mt][n][0], c[mt][n][1]));
                    tm[2 * mt + 1] = fmaxf(tm[2 * mt + 1], fmaxf(c[mt][n][2], c[mt][n][3]));
                }
            bool newmax = false;
            #pragma unroll
            for (int rg = 0; rg < 4; ++rg) {
                tm[rg] = fmaxf(tm[rg], __shfl_xor_sync(0xffffffffu, tm[rg], 1));
                tm[rg] = fmaxf(tm[rg], __shfl_xor_sync(0xffffffffu, tm[rg], 2));
                newmax |= (tm[rg] > M[rg]);
            }
            if (__any_sync(0xffffffffu, newmax)) {
                float sc[4];
                #pragma unroll
                for (int rg = 0; rg < 4; ++rg) {
                    const float Mn = fmaxf(M[rg], tm[rg]);
                    sc[rg] = __expf(M[rg] - Mn);
                    M[rg] = Mn;
                    Z[rg] *= sc[rg];
                }
                #pragma unroll
                for (int mt = 0; mt < 2; ++mt)
                    #pragma unroll
                    for (int n = 0; n < 16; ++n) {
                        o[mt][n][0] *= sc[2 * mt + 0]; o[mt][n][1] *= sc[2 * mt + 0];
                        o[mt][n][2] *= sc[2 * mt + 1]; o[mt][n][3] *= sc[2 * mt + 1];
                    }
            }
            uint32_t ph[2][4];
            #pragma unroll
            for (int mt = 0; mt < 2; ++mt) {
                const float* c0 = c[mt][2 * h + 0];
                const float* c1 = c[mt][2 * h + 1];
                float e0 = __expf(c0[0] - M[2 * mt]),     e1 = __expf(c0[1] - M[2 * mt]);
                float e2 = __expf(c0[2] - M[2 * mt + 1]), e3 = __expf(c0[3] - M[2 * mt + 1]);
                float f0 = __expf(c1[0] - M[2 * mt]),     f1 = __expf(c1[1] - M[2 * mt]);
                float f2 = __expf(c1[2] - M[2 * mt + 1]), f3 = __expf(c1[3] - M[2 * mt + 1]);
                Z[2 * mt + 0] += (e0 + e1) + (f0 + f1);
                Z[2 * mt + 1] += (e2 + e3) + (f2 + f3);
                ph[mt][0] = pack2h(__float2half_rn(e0), __float2half_rn(e1));
                ph[mt][1] = pack2h(__float2half_rn(e2), __float2half_rn(e3));
                ph[mt][2] = pack2h(__float2half_rn(f0), __float2half_rn(f1));
                ph[mt][3] = pack2h(__float2half_rn(f2), __float2half_rn(f3));
            }
            #pragma unroll
            for (int dp = 0; dp < 8; ++dp) {
                const uint32_t toff = (uint32_t)(h * 16 * PAD + dp * 16) * 2;
                uint32_t vf[4];
                ldsm_x4_t(vf, vv + vb4_off + toff);
                #pragma unroll
                for (int mt = 0; mt < 2; ++mt) {
                    mma16816(o[mt][2 * dp + 0], ph[mt], vf + 0);
                    mma16816(o[mt][2 * dp + 1], ph[mt], vf + 2);
                }
            }
        }
        __syncthreads();
    }

    // ---- quad-reduce Z; LayerNorm per row-group; write ----
    #pragma unroll
    for (int rg = 0; rg < 4; ++rg) {
        Z[rg] += __shfl_xor_sync(0xffffffffu, Z[rg], 1);
        Z[rg] += __shfl_xor_sync(0xffffffffu, Z[rg], 2);
    }
    #pragma unroll
    for (int rg = 0; rg < 4; ++rg) {
        const int mt = rg >> 1, ih = (rg & 1) * 2;
        const float zi = 1.0f / Z[rg];
        float s1 = 0.f, s2 = 0.f;
        #pragma unroll
        for (int n = 0; n < 16; ++n) {
            float x0 = o[mt][n][ih + 0] * zi, x1 = o[mt][n][ih + 1] * zi;
            s1 += x0 + x1;
            s2 += x0 * x0 + x1 * x1;
        }
        s1 += __shfl_xor_sync(0xffffffffu, s1, 1); s1 += __shfl_xor_sync(0xffffffffu, s1, 2);
        s2 += __shfl_xor_sync(0xffffffffu, s2, 1); s2 += __shfl_xor_sync(0xffffffffu, s2, 2);
        const float mu = s1 * (1.0f / 128.0f);
        const float va = fmaxf(s2 * (1.0f / 128.0f) - mu * mu, 0.0f);
        const float rs = rsqrtf(va + 1e-5f);
        float* orow = OUT + ((size_t)(b * LSEQ + q0 + 32 * w + 16 * mt + 8 * (rg & 1) + qr)) * DHEAD;
        #pragma unroll
        for (int n = 0; n < 16; ++n) {
            const int cb = 8 * n + qc2;
            const float2 g2 = *reinterpret_cast<const float2*>(GAMMA + cb);
            const float2 b2 = *reinterpret_cast<const float2*>(BETA + cb);
            float2 y;
            y.x = (o[mt][n][ih + 0] * zi - mu) * rs * g2.x + b2.x;
            y.y = (o[mt][n][ih + 1] * zi - mu) * rs * g2.y + b2.y;
            *reinterpret_cast<float2*>(orow + cb) = y;
        }
    }
}

extern "C" void kernel_launch(void* const* d_in, const int* in_sizes, int n_in,
                              void* d_out, int out_size) {
    (void)in_sizes; (void)n_in; (void)out_size;
    const float* q     = (const float*)d_in[0];
    const float* k     = (const float*)d_in[1];
    const float* v     = (const float*)d_in[2];
    const float* mask  = (const float*)d_in[3];
    const float* gamma = (const float*)d_in[4];
    const float* beta  = (const float*)d_in[5];
    float* out = (float*)d_out;

    cudaFuncSetAttribute(fmha_ln_hmma, cudaFuncAttributeMaxDynamicSharedMemorySize, SMEM_BYTES);

    const int total_f4 = BATCH * LSEQ * DHEAD / 4;
    prep_split<<<total_f4 / 256, 256>>>(q, k, v);
    fmha_ln_hmma<<<dim3(LSEQ / TQ, BATCH), THREADS, SMEM_BYTES>>>(mask, gamma, beta, out);
}